// round 14
// baseline (speedup 1.0000x reference)
#include <cuda_runtime.h>
#include <cstdint>

// Problem constants
#define NN_NODES 32768
#define E_MOL    131072
#define E_PRO    196608
#define HID      512
#define OUT_D    128
#define LAYERS   3
#define K_IN     96            // both input projections padded to 96
#define NH       (NN_NODES * HID)
#define NHALF    (NN_NODES / 2)

// ---------------- scratch (device globals) -----------------------------------
__device__ float g_h0m  [NH];
__device__ float g_prvm [NH];
__device__ float g_prvm2[NH];
__device__ float g_h0p  [NH];
__device__ float g_prvp [NH];
__device__ float g_prvp2[NH];
__device__ float g_supp [2 * NH];          // two planes (mol, pro)
__device__ float g_cat  [NN_NODES * 256];
__device__ float g_fc1  [NN_NODES * 1024];
__device__ float g_fc2  [NN_NODES * 512];
__device__ float g_xm   [NN_NODES * K_IN];
__device__ float g_xp   [NN_NODES * K_IN];
__device__ float g_wts  [2600000];         // transposed + tf32-rounded weights

// transposed weight offsets (all [N, Kpad] row-major)
#define WIN_M  0
#define WIN_P  49152
#define WS_M   98304
#define WS_P   884736
#define WOUT_M 1671168
#define WOUT_P 1736704
#define WFC1   1802240
#define WFC2   2064384

__device__ int   g_cnt [NN_NODES];
__device__ int   g_cur [NN_NODES];
__device__ int   g_cnt2[NN_NODES];
__device__ int   g_cur2[NN_NODES];
__device__ int   g_offm[NN_NODES + 1];
__device__ int   g_offp[NN_NODES + 1];
__device__ int   g_cscm[E_MOL];
__device__ int   g_cscp[E_PRO];
__device__ float g_dism[NN_NODES];
__device__ float g_disp[NN_NODES];

// ---------------- streams (static init: host-side, no device allocation) -----
static cudaStream_t g_s2, g_s3, g_s4;
static cudaEvent_t  g_evF, g_evJ, g_evPM, g_evPP;
static cudaEvent_t  g_evA[LAYERS], g_evB[LAYERS];   // mol pipeline
static cudaEvent_t  g_evC[LAYERS], g_evD[LAYERS];   // pro pipeline
static struct StreamInit {
    StreamInit() {
        cudaStreamCreateWithFlags(&g_s2, cudaStreamNonBlocking);
        cudaStreamCreateWithFlags(&g_s3, cudaStreamNonBlocking);
        cudaStreamCreateWithFlags(&g_s4, cudaStreamNonBlocking);
        cudaEventCreateWithFlags(&g_evF,  cudaEventDisableTiming);
        cudaEventCreateWithFlags(&g_evJ,  cudaEventDisableTiming);
        cudaEventCreateWithFlags(&g_evPM, cudaEventDisableTiming);
        cudaEventCreateWithFlags(&g_evPP, cudaEventDisableTiming);
        for (int l = 0; l < LAYERS; l++) {
            cudaEventCreateWithFlags(&g_evA[l], cudaEventDisableTiming);
            cudaEventCreateWithFlags(&g_evB[l], cudaEventDisableTiming);
            cudaEventCreateWithFlags(&g_evC[l], cudaEventDisableTiming);
            cudaEventCreateWithFlags(&g_evD[l], cudaEventDisableTiming);
        }
    }
} g_si;

// ---------------- helpers -----------------------------------------------------
__device__ __forceinline__ float tf32r(float f) {
    uint32_t u;
    asm("cvt.rna.tf32.f32 %0, %1;" : "=r"(u) : "f"(f));
    return __uint_as_float(u);
}

__global__ void zero_i_k(int* p, int n) {
    int i = blockIdx.x * blockDim.x + threadIdx.x;
    if (i < n) p[i] = 0;
}

__global__ void count_k(const int* __restrict__ col, int E, int* __restrict__ cnt) {
    int e = blockIdx.x * blockDim.x + threadIdx.x;
    if (e < E) atomicAdd(&cnt[col[e]], 1);
}

__global__ void scan_k(const int* __restrict__ cnt, int* __restrict__ offs,
                       int* __restrict__ cur, float* __restrict__ dis, int n) {
    __shared__ int sh[1024];
    int t = threadIdx.x;
    int per = n >> 10;
    int base = t * per;
    int s = 0;
    for (int j = 0; j < per; j++) s += cnt[base + j];
    sh[t] = s;
    __syncthreads();
    for (int off = 1; off < 1024; off <<= 1) {
        int v = (t >= off) ? sh[t - off] : 0;
        __syncthreads();
        sh[t] += v;
        __syncthreads();
    }
    int run = sh[t] - s;
    for (int j = 0; j < per; j++) {
        int c = cnt[base + j];
        offs[base + j] = run;
        cur[base + j]  = run;
        dis[base + j]  = rsqrtf((float)(c + 1));
        run += c;
    }
    if (t == 1023) offs[n] = run;
}

__global__ void scatter_k(const int* __restrict__ row, const int* __restrict__ col,
                          int E, int* __restrict__ cur, int* __restrict__ src) {
    int e = blockIdx.x * blockDim.x + threadIdx.x;
    if (e < E) {
        int c = col[e];
        int p = atomicAdd(&cur[c], 1);
        src[p] = row[e];
    }
}

// pad+round activations
__global__ void padround_k(const float* __restrict__ in, float* __restrict__ out,
                           int cin, int rows, int cout) {
    int i = blockIdx.x * blockDim.x + threadIdx.x;
    int total = rows * cout;
    if (i >= total) return;
    int r = i / cout, c = i - r * cout;
    out[i] = (c < cin) ? tf32r(in[(size_t)r * cin + c]) : 0.f;
}

// transpose+pad+round weights: in [Kin, Nn] -> out [Nn, Kpad]; optional +I
__global__ void padround_t_k(const float* __restrict__ in, float* __restrict__ out,
                             int Kin, int Nn, int Kpad, int addI) {
    int i = blockIdx.x * blockDim.x + threadIdx.x;
    int total = Nn * Kpad;
    if (i >= total) return;
    int n = i / Kpad, k = i - n * Kpad;
    float v = 0.f;
    if (k < Kin) {
        v = in[(size_t)k * Nn + n];
        if (addI && k == n) v += 1.0f;
        v = tf32r(v);
    }
    out[i] = v;
}

// ---------------- SpMM + support fuse (node-range version) --------------------
__global__ void spmm_k(const float* __restrict__ prev, const float* __restrict__ h0,
                       float* __restrict__ sup,
                       const int* __restrict__ offs, const int* __restrict__ srcs,
                       const float* __restrict__ dis, int ibase) {
    int i = blockIdx.x + ibase;
    int t = threadIdx.x;
    const float4* pv = (const float4*)prev;
    float di = dis[i];
    float4 p = pv[(size_t)i * 128 + t];
    float self = di * di;
    float4 acc = make_float4(self * p.x, self * p.y, self * p.z, self * p.w);
    int e0 = offs[i], e1 = offs[i + 1];
    for (int e = e0; e < e1; e++) {
        int s = srcs[e];
        float w = di * dis[s];
        float4 q = pv[(size_t)s * 128 + t];
        acc.x += w * q.x; acc.y += w * q.y; acc.z += w * q.z; acc.w += w * q.w;
    }
    float4 h = ((const float4*)h0)[(size_t)i * 128 + t];
    float4 o;
    o.x = tf32r(0.8f * acc.x + 0.2f * h.x);
    o.y = tf32r(0.8f * acc.y + 0.2f * h.y);
    o.z = tf32r(0.8f * acc.z + 0.2f * h.z);
    o.w = tf32r(0.8f * acc.w + 0.2f * h.w);
    ((float4*)sup)[(size_t)i * 128 + t] = o;
}

// ---------------- batched TF32 mma.sync GEMM (4 warps, 64x64 warp tile) -------
// z = blockIdx.z selects branch. A,Wt K-major pre-rounded tf32, K%32==0.
// MODE 0: out = relu(acc + bias[n]) ; MODE 1: out = relu(acc) + prev_in ;
// MODE 2: out = acc + bias[n] (strided ocol)
#define TBM 128
#define TBN 128
#define TILE_B 16384u
#define STAGE_B (2u * TILE_B)
#define GSMEM (3u * STAGE_B)     // 98304

__device__ __forceinline__ uint32_t s2u(const void* p) {
    uint32_t a;
    asm("{ .reg .u64 t; cvta.to.shared.u64 t, %1; cvt.u32.u64 %0, t; }" : "=r"(a) : "l"(p));
    return a;
}

__device__ __forceinline__ void cp16(uint32_t s, const float* g) {
    asm volatile("cp.async.cg.shared.global [%0], [%1], 16;" :: "r"(s), "l"(g));
}

__device__ __forceinline__ void mma_tf32(float* c, const uint32_t* a, const uint32_t* b) {
    asm volatile(
        "mma.sync.aligned.m16n8k8.row.col.f32.tf32.tf32.f32 "
        "{%0,%1,%2,%3}, {%4,%5,%6,%7}, {%8,%9}, {%0,%1,%2,%3};"
        : "+f"(c[0]), "+f"(c[1]), "+f"(c[2]), "+f"(c[3])
        : "r"(a[0]), "r"(a[1]), "r"(a[2]), "r"(a[3]), "r"(b[0]), "r"(b[1]));
}

#define LDSM4(r0, r1, r2, r3, a)                                                   \
    asm volatile("ldmatrix.sync.aligned.m8n8.x4.shared.b16 {%0,%1,%2,%3}, [%4];"   \
                 : "=r"(r0), "=r"(r1), "=r"(r2), "=r"(r3) : "r"(a))

template <int MODE, bool ROUND>
__global__ __launch_bounds__(128, 2)
void gemm2_k(const float* __restrict__ A0, const float* __restrict__ A1, int lda,
             const float* __restrict__ W0, const float* __restrict__ W1, int ldb,
             const float* __restrict__ b0, const float* __restrict__ b1,
             const float* __restrict__ p0, const float* __restrict__ p1,
             float* __restrict__ o0, float* __restrict__ o1,
             int K, int ldo, int oc0, int oc1) {
    extern __shared__ float smem[];
    uint32_t smemu = s2u(smem);

    int z = blockIdx.z;
    const float* A       = z ? A1 : A0;
    const float* Wt      = z ? W1 : W0;
    const float* bias    = z ? b1 : b0;
    const float* prev_in = z ? p1 : p0;
    float*       out     = z ? o1 : o0;
    int          ocol    = z ? oc1 : oc0;

    int tid = threadIdx.x;
    int bm = blockIdx.y * TBM;
    int bn = blockIdx.x * TBN;
    int warp = tid >> 5, lane = tid & 31;
    int wm = (warp >> 1) * 64;
    int wn = (warp & 1) * 64;
    int g = lane >> 2, tig = lane & 3;

    int seg = lane >> 3, rl = lane & 7;
    int rtile = ((seg & 1) << 3) + rl;
    int kqa = seg >> 1;

    uint32_t arow[4], brow[4];
#pragma unroll
    for (int mi = 0; mi < 4; mi++) arow[mi] = (uint32_t)(wm + mi * 16 + rtile) * 128u;
#pragma unroll
    for (int nj = 0; nj < 4; nj++) brow[nj] = (uint32_t)(wn + nj * 16 + rtile) * 128u;

    float acc[4][8][4];
#pragma unroll
    for (int mi = 0; mi < 4; mi++)
#pragma unroll
        for (int ni = 0; ni < 8; ni++)
#pragma unroll
            for (int e = 0; e < 4; e++) acc[mi][ni][e] = 0.f;

    auto load_tile = [&](int kt, int st) {
        uint32_t sa = smemu + st * STAGE_B;
        uint32_t sb = sa + TILE_B;
        const float* Ab = A + (size_t)bm * lda + kt * 32;
        const float* Bb = Wt + (size_t)bn * ldb + kt * 32;
#pragma unroll
        for (int it = 0; it < 8; it++) {
            int idx = it * 128 + tid;
            int row = idx >> 3, q = idx & 7;
            uint32_t sw = (uint32_t)row * 128u + (uint32_t)((q ^ (row & 7)) << 4);
            cp16(sa + sw, Ab + (size_t)row * lda + q * 4);
        }
#pragma unroll
        for (int it = 0; it < 8; it++) {
            int idx = it * 128 + tid;
            int row = idx >> 3, q = idx & 7;
            uint32_t sw = (uint32_t)row * 128u + (uint32_t)((q ^ (row & 7)) << 4);
            cp16(sb + sw, Bb + (size_t)row * ldb + q * 4);
        }
        asm volatile("cp.async.commit_group;" ::: "memory");
    };

    int nk = K >> 5;
    load_tile(0, 0);
    if (nk > 1) load_tile(1, 1);

    for (int kt = 0; kt < nk; kt++) {
        if (kt < nk - 1) asm volatile("cp.async.wait_group 1;" ::: "memory");
        else             asm volatile("cp.async.wait_group 0;" ::: "memory");
        __syncthreads();
        if (kt + 2 < nk) load_tile(kt + 2, (kt + 2) % 3);

        uint32_t sa = smemu + (kt % 3) * STAGE_B;
        uint32_t sb = sa + TILE_B;
#pragma unroll
        for (int ks = 0; ks < 4; ks++) {
            uint32_t kx = (uint32_t)(((ks * 2 + kqa) ^ rl) << 4);
            uint32_t af[4][4], bf[8][2];
#pragma unroll
            for (int mi = 0; mi < 4; mi++)
                LDSM4(af[mi][0], af[mi][1], af[mi][2], af[mi][3], sa + arow[mi] + kx);
#pragma unroll
            for (int nj = 0; nj < 4; nj++)
                LDSM4(bf[2 * nj][0], bf[2 * nj + 1][0], bf[2 * nj][1], bf[2 * nj + 1][1],
                      sb + brow[nj] + kx);
#pragma unroll
            for (int mi = 0; mi < 4; mi++)
#pragma unroll
                for (int ni = 0; ni < 8; ni++) mma_tf32(acc[mi][ni], af[mi], bf[ni]);
        }
        // no loop-end barrier: next iteration's barrier precedes first write to
        // any stage read this iteration (3-stage WAR safety).
    }

#pragma unroll
    for (int mi = 0; mi < 4; mi++)
#pragma unroll
        for (int ni = 0; ni < 8; ni++) {
            int r = bm + wm + mi * 16 + g;
            int c = bn + wn + ni * 8 + 2 * tig;
#pragma unroll
            for (int e = 0; e < 4; e++) {
                int rr = r + ((e >= 2) ? 8 : 0);
                int cc = c + (e & 1);
                float v = acc[mi][ni][e];
                if (MODE == 0 || MODE == 2) {
                    v += bias[cc];
                    if (MODE == 0) v = fmaxf(v, 0.f);
                    if (ROUND) v = tf32r(v);
                    out[(size_t)rr * ldo + ocol + cc] = v;
                } else {
                    size_t idx = (size_t)rr * ldo + cc;
                    v = fmaxf(v, 0.f) + prev_in[idx];
                    if (ROUND) v = tf32r(v);
                    out[idx] = v;
                }
            }
        }
}

// ---------------- final GEMV --------------------------------------------------
__global__ void gemv_k(const float* __restrict__ X, const float* __restrict__ w,
                       const float* __restrict__ b, float* __restrict__ out) {
    int row = blockIdx.x * 4 + (threadIdx.x >> 5);
    int lane = threadIdx.x & 31;
    const float* x = X + (size_t)row * 512;
    float s = 0.f;
#pragma unroll
    for (int j = 0; j < 16; j++) s += x[lane + j * 32] * w[lane + j * 32];
#pragma unroll
    for (int o = 16; o > 0; o >>= 1) s += __shfl_xor_sync(0xFFFFFFFFu, s, o);
    if (lane == 0) out[row] = s + b[0];
}

// ---------------- launch ------------------------------------------------------
static void* sym(const void* s) {
    void* p = nullptr;
    cudaGetSymbolAddress(&p, (const void*)s);
    return p;
}

extern "C" void kernel_launch(void* const* d_in, const int* in_sizes, int n_in,
                              void* d_out, int out_size) {
    const float* mol_x     = (const float*)d_in[0];
    const int*   mol_ei    = (const int*)d_in[1];
    const float* pro_x     = (const float*)d_in[2];
    const int*   pro_ei    = (const int*)d_in[3];
    const float* mol_w_in  = (const float*)d_in[4];
    const float* mol_b_in  = (const float*)d_in[5];
    const float* mol_ws    = (const float*)d_in[6];
    const float* mol_w_out = (const float*)d_in[7];
    const float* mol_b_out = (const float*)d_in[8];
    const float* pro_w_in  = (const float*)d_in[9];
    const float* pro_b_in  = (const float*)d_in[10];
    const float* pro_ws    = (const float*)d_in[11];
    const float* pro_w_out = (const float*)d_in[12];
    const float* pro_b_out = (const float*)d_in[13];
    const float* w_fc1     = (const float*)d_in[14];
    const float* b_fc1     = (const float*)d_in[15];
    const float* w_fc2     = (const float*)d_in[16];
    const float* b_fc2     = (const float*)d_in[17];
    const float* w_o       = (const float*)d_in[18];
    const float* b_o       = (const float*)d_in[19];
    float* out = (float*)d_out;

    float* h0m   = (float*)sym(g_h0m);
    float* prvm  = (float*)sym(g_prvm);
    float* prvm2 = (float*)sym(g_prvm2);
    float* h0p   = (float*)sym(g_h0p);
    float* prvp  = (float*)sym(g_prvp);
    float* prvp2 = (float*)sym(g_prvp2);
    float* supp  = (float*)sym(g_supp);
    float* cat   = (float*)sym(g_cat);
    float* fc1   = (float*)sym(g_fc1);
    float* fc2   = (float*)sym(g_fc2);
    float* xm    = (float*)sym(g_xm);
    float* xp    = (float*)sym(g_xp);
    float* wts   = (float*)sym(g_wts);
    int*   cnt   = (int*)sym(g_cnt);
    int*   cur   = (int*)sym(g_cur);
    int*   cnt2  = (int*)sym(g_cnt2);
    int*   cur2  = (int*)sym(g_cur2);
    int*   offm  = (int*)sym(g_offm);
    int*   offp  = (int*)sym(g_offp);
    int*   cscm  = (int*)sym(g_cscm);
    int*   cscp  = (int*)sym(g_cscp);
    float* dism  = (float*)sym(g_dism);
    float* disp  = (float*)sym(g_disp);

    const int N = NN_NODES;

    cudaFuncSetAttribute(gemm2_k<0, true>,  cudaFuncAttributeMaxDynamicSharedMemorySize, GSMEM);
    cudaFuncSetAttribute(gemm2_k<0, false>, cudaFuncAttributeMaxDynamicSharedMemorySize, GSMEM);
    cudaFuncSetAttribute(gemm2_k<1, true>,  cudaFuncAttributeMaxDynamicSharedMemorySize, GSMEM);
    cudaFuncSetAttribute(gemm2_k<2, true>,  cudaFuncAttributeMaxDynamicSharedMemorySize, GSMEM);

    const int GY  = N / TBM;        // 256
    const int GYH = NHALF / TBM;    // 128
    const size_t HOFF = (size_t)NHALF * HID;   // element offset of half 1
    cudaStream_t sM = 0, sP = g_s2, sC = g_s3, sD = g_s4;

    // ---- fork: bring side streams into the capture graph ----
    cudaEventRecord(g_evF, sM);
    cudaStreamWaitEvent(sP, g_evF, 0);
    cudaStreamWaitEvent(sC, g_evF, 0);
    cudaStreamWaitEvent(sD, g_evF, 0);

    auto prt = [&](const float* in, float* o, int Kin, int Nn, int Kpad, int addI,
                   cudaStream_t st) {
        int tot = Nn * Kpad;
        padround_t_k<<<(tot + 255) / 256, 256, 0, st>>>(in, o, Kin, Nn, Kpad, addI);
    };

    // ============ MOL prep on sC: CSC + layer/out/head weight transposes ======
    zero_i_k<<<(N + 255) / 256, 256, 0, sC>>>(cnt, N);
    count_k<<<(E_MOL + 255) / 256, 256, 0, sC>>>(mol_ei + E_MOL, E_MOL, cnt);
    scan_k<<<1, 1024, 0, sC>>>(cnt, offm, cur, dism, N);
    scatter_k<<<(E_MOL + 255) / 256, 256, 0, sC>>>(mol_ei, mol_ei + E_MOL, E_MOL, cur, cscm);
    for (int l = 0; l < LAYERS; l++)
        prt(mol_ws + (size_t)l * HID * HID, wts + WS_M + (size_t)l * HID * HID, HID, HID, HID, 1, sC);
    prt(mol_w_out, wts + WOUT_M, HID, OUT_D, HID, 0, sC);
    prt(w_fc1, wts + WFC1, 256, 1024, 256, 0, sC);
    prt(w_fc2, wts + WFC2, 1024, 512, 1024, 0, sC);
    cudaEventRecord(g_evPM, sC);

    // ============ PRO prep on sD ============
    zero_i_k<<<(N + 255) / 256, 256, 0, sD>>>(cnt2, N);
    count_k<<<(E_PRO + 255) / 256, 256, 0, sD>>>(pro_ei + E_PRO, E_PRO, cnt2);
    scan_k<<<1, 1024, 0, sD>>>(cnt2, offp, cur2, disp, N);
    scatter_k<<<(E_PRO + 255) / 256, 256, 0, sD>>>(pro_ei, pro_ei + E_PRO, E_PRO, cur2, cscp);
    for (int l = 0; l < LAYERS; l++)
        prt(pro_ws + (size_t)l * HID * HID, wts + WS_P + (size_t)l * HID * HID, HID, HID, HID, 1, sD);
    prt(pro_w_out, wts + WOUT_P, HID, OUT_D, HID, 0, sD);
    cudaEventRecord(g_evPP, sD);

    // =================== MOL chain: pipelined layers on sM + sC ===============
    padround_k<<<(N * K_IN + 255) / 256, 256, 0, sM>>>(mol_x, xm, 78, N, K_IN);
    prt(mol_w_in, wts + WIN_M, 78, HID, K_IN, 0, sM);
    gemm2_k<0, true><<<dim3(HID / TBN, GY, 1), 128, GSMEM, sM>>>(
        xm, xm, K_IN, wts + WIN_M, wts + WIN_M, K_IN,
        mol_b_in, mol_b_in, nullptr, nullptr, h0m, h0m, K_IN, HID, 0, 0);

    cudaStreamWaitEvent(sM, g_evPM, 0);   // CSC_m + ws_m ready (sC idle after this)
    for (int l = 0; l < LAYERS; l++) {
        // ping-pong: L0 h0m->prvm, L1 prvm->prvm2, L2 prvm2->prvm
        const float* pin  = (l == 0) ? h0m : ((l & 1) ? prvm : prvm2);
        float*       pout = (l & 1) ? prvm2 : prvm;
        const float* w = wts + WS_M + (size_t)l * HID * HID;
        // half 0 on sM
        spmm_k<<<NHALF, 128, 0, sM>>>(pin, h0m, supp, offm, cscm, dism, 0);
        cudaEventRecord(g_evA[l], sM);
        gemm2_k<1, true><<<dim3(HID / TBN, GYH, 1), 128, GSMEM, sM>>>(
            supp, supp, HID, w, w, HID, nullptr, nullptr,
            pin, pin, pout, pout, HID, HID, 0, 0);
        // half 1 on sC (staggered)
        cudaStreamWaitEvent(sC, g_evA[l], 0);
        spmm_k<<<NHALF, 128, 0, sC>>>(pin, h0m, supp, offm, cscm, dism, NHALF);
        gemm2_k<1, true><<<dim3(HID / TBN, GYH, 1), 128, GSMEM, sC>>>(
            supp + HOFF, supp + HOFF, HID, w, w, HID, nullptr, nullptr,
            pin + HOFF, pin + HOFF, pout + HOFF, pout + HOFF, HID, HID, 0, 0);
        cudaEventRecord(g_evB[l], sC);
        cudaStreamWaitEvent(sM, g_evB[l], 0);
    }
    // final mol prev: L2 wrote prvm

    // =================== PRO chain: pipelined layers on sP + sD ===============
    padround_k<<<(N * K_IN + 255) / 256, 256, 0, sP>>>(pro_x, xp, 54, N, K_IN);
    prt(pro_w_in, wts + WIN_P, 54, HID, K_IN, 0, sP);
    gemm2_k<0, true><<<dim3(HID / TBN, GY, 1), 128, GSMEM, sP>>>(
        xp, xp, K_IN, wts + WIN_P, wts + WIN_P, K_IN,
        pro_b_in, pro_b_in, nullptr, nullptr, h0p, h0p, K_IN, HID, 0, 0);

    cudaStreamWaitEvent(sP, g_evPP, 0);   // CSC_p + ws_p ready (sD idle after this)
    {
        float* suppP = supp + NH;
        for (int l = 0; l < LAYERS; l++) {
            // ping-pong: L0 h0p->prvp, L1 prvp->prvp2, L2 prvp2->prvp
            const float* pin  = (l == 0) ? h0p : ((l & 1) ? prvp : prvp2);
            float*       pout = (l & 1) ? prvp2 : prvp;
            const float* w = wts + WS_P + (size_t)l * HID * HID;
            // half 0 on sP
            spmm_k<<<NHALF, 128, 0, sP>>>(pin, h0p, suppP, offp, cscp, disp, 0);
            cudaEventRecord(g_evC[l], sP);
            gemm2_k<1, true><<<dim3(HID / TBN, GYH, 1), 128, GSMEM, sP>>>(
                suppP, suppP, HID, w, w, HID, nullptr, nullptr,
                pin, pin, pout, pout, HID, HID, 0, 0);
            // half 1 on sD (staggered)
            cudaStreamWaitEvent(sD, g_evC[l], 0);
            spmm_k<<<NHALF, 128, 0, sD>>>(pin, h0p, suppP, offp, cscp, disp, NHALF);
            gemm2_k<1, true><<<dim3(HID / TBN, GYH, 1), 128, GSMEM, sD>>>(
                suppP + HOFF, suppP + HOFF, HID, w, w, HID, nullptr, nullptr,
                pin + HOFF, pin + HOFF, pout + HOFF, pout + HOFF, HID, HID, 0, 0);
            cudaEventRecord(g_evD[l], sD);
            cudaStreamWaitEvent(sP, g_evD[l], 0);
        }
    }

    // ---- join ----
    cudaEventRecord(g_evJ, sP);
    cudaStreamWaitEvent(sM, g_evJ, 0);

    // ---- batched output projections into concat buffer [N, 256] ----
    gemm2_k<2, true><<<dim3(OUT_D / TBN, GY, 2), 128, GSMEM, sM>>>(
        prvm, prvp, HID, wts + WOUT_M, wts + WOUT_P, HID,
        mol_b_out, pro_b_out, nullptr, nullptr, cat, cat, HID, 256, 0, OUT_D);

    // ---- MLP head ----
    gemm2_k<0, true><<<dim3(1024 / TBN, GY, 1), 128, GSMEM, sM>>>(
        cat, cat, 256, wts + WFC1, wts + WFC1, 256,
        b_fc1, b_fc1, nullptr, nullptr, fc1, fc1, 256, 1024, 0, 0);
    gemm2_k<0, false><<<dim3(512 / TBN, GY, 1), 128, GSMEM, sM>>>(
        fc1, fc1, 1024, wts + WFC2, wts + WFC2, 1024,
        b_fc2, b_fc2, nullptr, nullptr, fc2, fc2, 1024, 512, 0, 0);
    gemv_k<<<N / 4, 128, 0, sM>>>(fc2, w_o, b_o, out);
}

// round 15
// speedup vs baseline: 1.0677x; 1.0677x over previous
#include <cuda_runtime.h>
#include <cstdint>

// Problem constants
#define NN_NODES 32768
#define E_MOL    131072
#define E_PRO    196608
#define HID      512
#define OUT_D    128
#define LAYERS   3
#define K_IN     96            // both input projections padded to 96
#define NH       (NN_NODES * HID)

// ---------------- scratch (device globals) -----------------------------------
__device__ float g_h0m [NH];
__device__ float g_prvm[NH];
__device__ float g_h0p [NH];
__device__ float g_prvp[NH];
__device__ float g_supp[2 * NH];           // two planes (mol, pro)
__device__ float g_cat [NN_NODES * 256];
__device__ float g_fc1 [NN_NODES * 1024];
__device__ float g_xm  [NN_NODES * K_IN];
__device__ float g_xp  [NN_NODES * K_IN];
__device__ float g_wts [2600000];          // transposed + tf32-rounded weights

// transposed weight offsets (all [N, Kpad] row-major)
#define WIN_M  0
#define WIN_P  49152
#define WS_M   98304
#define WS_P   884736
#define WOUT_M 1671168
#define WOUT_P 1736704
#define WFC1   1802240
#define WFC2   2064384

__device__ int   g_cnt [NN_NODES];
__device__ int   g_cur [NN_NODES];
__device__ int   g_cnt2[NN_NODES];
__device__ int   g_cur2[NN_NODES];
__device__ int   g_offm[NN_NODES + 1];
__device__ int   g_offp[NN_NODES + 1];
__device__ int   g_cscm[E_MOL];
__device__ int   g_cscp[E_PRO];
__device__ float g_dism[NN_NODES];
__device__ float g_disp[NN_NODES];

// ---------------- streams (static init: host-side, no device allocation) -----
static cudaStream_t g_s2, g_s3, g_s4;
static cudaEvent_t  g_evF, g_evJ, g_evPM, g_evPP;
static struct StreamInit {
    StreamInit() {
        cudaStreamCreateWithFlags(&g_s2, cudaStreamNonBlocking);
        cudaStreamCreateWithFlags(&g_s3, cudaStreamNonBlocking);
        cudaStreamCreateWithFlags(&g_s4, cudaStreamNonBlocking);
        cudaEventCreateWithFlags(&g_evF,  cudaEventDisableTiming);
        cudaEventCreateWithFlags(&g_evJ,  cudaEventDisableTiming);
        cudaEventCreateWithFlags(&g_evPM, cudaEventDisableTiming);
        cudaEventCreateWithFlags(&g_evPP, cudaEventDisableTiming);
    }
} g_si;

// ---------------- helpers -----------------------------------------------------
__device__ __forceinline__ float tf32r(float f) {
    uint32_t u;
    asm("cvt.rna.tf32.f32 %0, %1;" : "=r"(u) : "f"(f));
    return __uint_as_float(u);
}

__global__ void zero_i_k(int* p, int n) {
    int i = blockIdx.x * blockDim.x + threadIdx.x;
    if (i < n) p[i] = 0;
}

// init final output with b_o (MODE-5 fc2 epilogue atomicAdds onto it)
__global__ void out_init_k(float* out, const float* __restrict__ b, int n) {
    int i = blockIdx.x * blockDim.x + threadIdx.x;
    if (i < n) out[i] = b[0];
}

__global__ void count_k(const int* __restrict__ col, int E, int* __restrict__ cnt) {
    int e = blockIdx.x * blockDim.x + threadIdx.x;
    if (e < E) atomicAdd(&cnt[col[e]], 1);
}

__global__ void scan_k(const int* __restrict__ cnt, int* __restrict__ offs,
                       int* __restrict__ cur, float* __restrict__ dis, int n) {
    __shared__ int sh[1024];
    int t = threadIdx.x;
    int per = n >> 10;
    int base = t * per;
    int s = 0;
    for (int j = 0; j < per; j++) s += cnt[base + j];
    sh[t] = s;
    __syncthreads();
    for (int off = 1; off < 1024; off <<= 1) {
        int v = (t >= off) ? sh[t - off] : 0;
        __syncthreads();
        sh[t] += v;
        __syncthreads();
    }
    int run = sh[t] - s;
    for (int j = 0; j < per; j++) {
        int c = cnt[base + j];
        offs[base + j] = run;
        cur[base + j]  = run;
        dis[base + j]  = rsqrtf((float)(c + 1));
        run += c;
    }
    if (t == 1023) offs[n] = run;
}

__global__ void scatter_k(const int* __restrict__ row, const int* __restrict__ col,
                          int E, int* __restrict__ cur, int* __restrict__ src) {
    int e = blockIdx.x * blockDim.x + threadIdx.x;
    if (e < E) {
        int c = col[e];
        int p = atomicAdd(&cur[c], 1);
        src[p] = row[e];
    }
}

// pad+round activations
__global__ void padround_k(const float* __restrict__ in, float* __restrict__ out,
                           int cin, int rows, int cout) {
    int i = blockIdx.x * blockDim.x + threadIdx.x;
    int total = rows * cout;
    if (i >= total) return;
    int r = i / cout, c = i - r * cout;
    out[i] = (c < cin) ? tf32r(in[(size_t)r * cin + c]) : 0.f;
}

// transpose+pad+round weights: in [Kin, Nn] -> out [Nn, Kpad]; optional +I
__global__ void padround_t_k(const float* __restrict__ in, float* __restrict__ out,
                             int Kin, int Nn, int Kpad, int addI) {
    int i = blockIdx.x * blockDim.x + threadIdx.x;
    int total = Nn * Kpad;
    if (i >= total) return;
    int n = i / Kpad, k = i - n * Kpad;
    float v = 0.f;
    if (k < Kin) {
        v = in[(size_t)k * Nn + n];
        if (addI && k == n) v += 1.0f;
        v = tf32r(v);
    }
    out[i] = v;
}

// ---------------- SpMM + support fuse (R7/R10-verbatim) -----------------------
__global__ void spmm_k(const float* __restrict__ prev, const float* __restrict__ h0,
                       float* __restrict__ sup,
                       const int* __restrict__ offs, const int* __restrict__ srcs,
                       const float* __restrict__ dis) {
    int i = blockIdx.x;
    int t = threadIdx.x;
    const float4* pv = (const float4*)prev;
    float di = dis[i];
    float4 p = pv[(size_t)i * 128 + t];
    float self = di * di;
    float4 acc = make_float4(self * p.x, self * p.y, self * p.z, self * p.w);
    int e0 = offs[i], e1 = offs[i + 1];
    for (int e = e0; e < e1; e++) {
        int s = srcs[e];
        float w = di * dis[s];
        float4 q = pv[(size_t)s * 128 + t];
        acc.x += w * q.x; acc.y += w * q.y; acc.z += w * q.z; acc.w += w * q.w;
    }
    float4 h = ((const float4*)h0)[(size_t)i * 128 + t];
    float4 o;
    o.x = tf32r(0.8f * acc.x + 0.2f * h.x);
    o.y = tf32r(0.8f * acc.y + 0.2f * h.y);
    o.z = tf32r(0.8f * acc.z + 0.2f * h.z);
    o.w = tf32r(0.8f * acc.w + 0.2f * h.w);
    ((float4*)sup)[(size_t)i * 128 + t] = o;
}

// ---------------- batched TF32 mma.sync GEMM (4 warps, 64x64 warp tile) -------
// z = blockIdx.z selects branch. A,Wt K-major pre-rounded tf32, K%32==0.
// MODE 0: out = relu(acc + bias[n])
// MODE 1: out = relu(acc) + prev_in
// MODE 2: out = acc + bias[n] (strided ocol)
// MODE 5: fused fc2+gemv: v = relu(acc + bias[n]); atomicAdd(out[row], v*wvec[n])
//         (prev_in carries wvec; out is the final [N,1] result pre-set to b_o)
#define TBM 128
#define TBN 128
#define TILE_B 16384u
#define STAGE_B (2u * TILE_B)
#define GSMEM (3u * STAGE_B)     // 98304

__device__ __forceinline__ uint32_t s2u(const void* p) {
    uint32_t a;
    asm("{ .reg .u64 t; cvta.to.shared.u64 t, %1; cvt.u32.u64 %0, t; }" : "=r"(a) : "l"(p));
    return a;
}

__device__ __forceinline__ void cp16(uint32_t s, const float* g) {
    asm volatile("cp.async.cg.shared.global [%0], [%1], 16;" :: "r"(s), "l"(g));
}

__device__ __forceinline__ void mma_tf32(float* c, const uint32_t* a, const uint32_t* b) {
    asm volatile(
        "mma.sync.aligned.m16n8k8.row.col.f32.tf32.tf32.f32 "
        "{%0,%1,%2,%3}, {%4,%5,%6,%7}, {%8,%9}, {%0,%1,%2,%3};"
        : "+f"(c[0]), "+f"(c[1]), "+f"(c[2]), "+f"(c[3])
        : "r"(a[0]), "r"(a[1]), "r"(a[2]), "r"(a[3]), "r"(b[0]), "r"(b[1]));
}

#define LDSM4(r0, r1, r2, r3, a)                                                   \
    asm volatile("ldmatrix.sync.aligned.m8n8.x4.shared.b16 {%0,%1,%2,%3}, [%4];"   \
                 : "=r"(r0), "=r"(r1), "=r"(r2), "=r"(r3) : "r"(a))

template <int MODE, bool ROUND>
__global__ __launch_bounds__(128, 2)
void gemm2_k(const float* __restrict__ A0, const float* __restrict__ A1, int lda,
             const float* __restrict__ W0, const float* __restrict__ W1, int ldb,
             const float* __restrict__ b0, const float* __restrict__ b1,
             const float* __restrict__ p0, const float* __restrict__ p1,
             float* __restrict__ o0, float* __restrict__ o1,
             int K, int ldo, int oc0, int oc1) {
    extern __shared__ float smem[];
    uint32_t smemu = s2u(smem);

    int z = blockIdx.z;
    const float* A       = z ? A1 : A0;
    const float* Wt      = z ? W1 : W0;
    const float* bias    = z ? b1 : b0;
    const float* prev_in = z ? p1 : p0;
    float*       out     = z ? o1 : o0;
    int          ocol    = z ? oc1 : oc0;

    int tid = threadIdx.x;
    int bm = blockIdx.y * TBM;
    int bn = blockIdx.x * TBN;
    int warp = tid >> 5, lane = tid & 31;
    int wm = (warp >> 1) * 64;
    int wn = (warp & 1) * 64;
    int g = lane >> 2, tig = lane & 3;

    int seg = lane >> 3, rl = lane & 7;
    int rtile = ((seg & 1) << 3) + rl;
    int kqa = seg >> 1;

    uint32_t arow[4], brow[4];
#pragma unroll
    for (int mi = 0; mi < 4; mi++) arow[mi] = (uint32_t)(wm + mi * 16 + rtile) * 128u;
#pragma unroll
    for (int nj = 0; nj < 4; nj++) brow[nj] = (uint32_t)(wn + nj * 16 + rtile) * 128u;

    float acc[4][8][4];
#pragma unroll
    for (int mi = 0; mi < 4; mi++)
#pragma unroll
        for (int ni = 0; ni < 8; ni++)
#pragma unroll
            for (int e = 0; e < 4; e++) acc[mi][ni][e] = 0.f;

    auto load_tile = [&](int kt, int st) {
        uint32_t sa = smemu + st * STAGE_B;
        uint32_t sb = sa + TILE_B;
        const float* Ab = A + (size_t)bm * lda + kt * 32;
        const float* Bb = Wt + (size_t)bn * ldb + kt * 32;
#pragma unroll
        for (int it = 0; it < 8; it++) {
            int idx = it * 128 + tid;
            int row = idx >> 3, q = idx & 7;
            uint32_t sw = (uint32_t)row * 128u + (uint32_t)((q ^ (row & 7)) << 4);
            cp16(sa + sw, Ab + (size_t)row * lda + q * 4);
        }
#pragma unroll
        for (int it = 0; it < 8; it++) {
            int idx = it * 128 + tid;
            int row = idx >> 3, q = idx & 7;
            uint32_t sw = (uint32_t)row * 128u + (uint32_t)((q ^ (row & 7)) << 4);
            cp16(sb + sw, Bb + (size_t)row * ldb + q * 4);
        }
        asm volatile("cp.async.commit_group;" ::: "memory");
    };

    int nk = K >> 5;
    load_tile(0, 0);
    if (nk > 1) load_tile(1, 1);

    for (int kt = 0; kt < nk; kt++) {
        if (kt < nk - 1) asm volatile("cp.async.wait_group 1;" ::: "memory");
        else             asm volatile("cp.async.wait_group 0;" ::: "memory");
        __syncthreads();
        if (kt + 2 < nk) load_tile(kt + 2, (kt + 2) % 3);

        uint32_t sa = smemu + (kt % 3) * STAGE_B;
        uint32_t sb = sa + TILE_B;
#pragma unroll
        for (int ks = 0; ks < 4; ks++) {
            uint32_t kx = (uint32_t)(((ks * 2 + kqa) ^ rl) << 4);
            uint32_t af[4][4], bf[8][2];
#pragma unroll
            for (int mi = 0; mi < 4; mi++)
                LDSM4(af[mi][0], af[mi][1], af[mi][2], af[mi][3], sa + arow[mi] + kx);
#pragma unroll
            for (int nj = 0; nj < 4; nj++)
                LDSM4(bf[2 * nj][0], bf[2 * nj + 1][0], bf[2 * nj][1], bf[2 * nj + 1][1],
                      sb + brow[nj] + kx);
#pragma unroll
            for (int mi = 0; mi < 4; mi++)
#pragma unroll
                for (int ni = 0; ni < 8; ni++) mma_tf32(acc[mi][ni], af[mi], bf[ni]);
        }
        // no loop-end barrier: next iteration's barrier precedes first write to
        // any stage read this iteration (3-stage WAR safety).
    }

    if (MODE == 5) {
        // fused fc2 + gemv: per-thread row partials of relu(acc+bias) . wvec
        float rowdot[4][2];
#pragma unroll
        for (int mi = 0; mi < 4; mi++) { rowdot[mi][0] = 0.f; rowdot[mi][1] = 0.f; }
#pragma unroll
        for (int mi = 0; mi < 4; mi++)
#pragma unroll
            for (int ni = 0; ni < 8; ni++) {
                int c = bn + wn + ni * 8 + 2 * tig;
#pragma unroll
                for (int e = 0; e < 4; e++) {
                    int cc = c + (e & 1);
                    float v = fmaxf(acc[mi][ni][e] + bias[cc], 0.f);
                    rowdot[mi][e >> 1] += v * prev_in[cc];
                }
            }
#pragma unroll
        for (int mi = 0; mi < 4; mi++)
#pragma unroll
            for (int h = 0; h < 2; h++) {
                int rr = bm + wm + mi * 16 + g + h * 8;
                atomicAdd(&out[rr], rowdot[mi][h]);
            }
        return;
    }

#pragma unroll
    for (int mi = 0; mi < 4; mi++)
#pragma unroll
        for (int ni = 0; ni < 8; ni++) {
            int r = bm + wm + mi * 16 + g;
            int c = bn + wn + ni * 8 + 2 * tig;
#pragma unroll
            for (int e = 0; e < 4; e++) {
                int rr = r + ((e >= 2) ? 8 : 0);
                int cc = c + (e & 1);
                float v = acc[mi][ni][e];
                if (MODE == 0 || MODE == 2) {
                    v += bias[cc];
                    if (MODE == 0) v = fmaxf(v, 0.f);
                    if (ROUND) v = tf32r(v);
                    out[(size_t)rr * ldo + ocol + cc] = v;
                } else {
                    size_t idx = (size_t)rr * ldo + cc;
                    v = fmaxf(v, 0.f) + prev_in[idx];
                    if (ROUND) v = tf32r(v);
                    out[idx] = v;
                }
            }
        }
}

// ---------------- launch ------------------------------------------------------
static void* sym(const void* s) {
    void* p = nullptr;
    cudaGetSymbolAddress(&p, (const void*)s);
    return p;
}

extern "C" void kernel_launch(void* const* d_in, const int* in_sizes, int n_in,
                              void* d_out, int out_size) {
    const float* mol_x     = (const float*)d_in[0];
    const int*   mol_ei    = (const int*)d_in[1];
    const float* pro_x     = (const float*)d_in[2];
    const int*   pro_ei    = (const int*)d_in[3];
    const float* mol_w_in  = (const float*)d_in[4];
    const float* mol_b_in  = (const float*)d_in[5];
    const float* mol_ws    = (const float*)d_in[6];
    const float* mol_w_out = (const float*)d_in[7];
    const float* mol_b_out = (const float*)d_in[8];
    const float* pro_w_in  = (const float*)d_in[9];
    const float* pro_b_in  = (const float*)d_in[10];
    const float* pro_ws    = (const float*)d_in[11];
    const float* pro_w_out = (const float*)d_in[12];
    const float* pro_b_out = (const float*)d_in[13];
    const float* w_fc1     = (const float*)d_in[14];
    const float* b_fc1     = (const float*)d_in[15];
    const float* w_fc2     = (const float*)d_in[16];
    const float* b_fc2     = (const float*)d_in[17];
    const float* w_o       = (const float*)d_in[18];
    const float* b_o       = (const float*)d_in[19];
    float* out = (float*)d_out;

    float* h0m  = (float*)sym(g_h0m);
    float* prvm = (float*)sym(g_prvm);
    float* h0p  = (float*)sym(g_h0p);
    float* prvp = (float*)sym(g_prvp);
    float* supp = (float*)sym(g_supp);
    float* cat  = (float*)sym(g_cat);
    float* fc1  = (float*)sym(g_fc1);
    float* xm   = (float*)sym(g_xm);
    float* xp   = (float*)sym(g_xp);
    float* wts  = (float*)sym(g_wts);
    int*   cnt  = (int*)sym(g_cnt);
    int*   cur  = (int*)sym(g_cur);
    int*   cnt2 = (int*)sym(g_cnt2);
    int*   cur2 = (int*)sym(g_cur2);
    int*   offm = (int*)sym(g_offm);
    int*   offp = (int*)sym(g_offp);
    int*   cscm = (int*)sym(g_cscm);
    int*   cscp = (int*)sym(g_cscp);
    float* dism = (float*)sym(g_dism);
    float* disp = (float*)sym(g_disp);

    const int N = NN_NODES;

    cudaFuncSetAttribute(gemm2_k<0, true>,  cudaFuncAttributeMaxDynamicSharedMemorySize, GSMEM);
    cudaFuncSetAttribute(gemm2_k<1, true>,  cudaFuncAttributeMaxDynamicSharedMemorySize, GSMEM);
    cudaFuncSetAttribute(gemm2_k<2, true>,  cudaFuncAttributeMaxDynamicSharedMemorySize, GSMEM);
    cudaFuncSetAttribute(gemm2_k<5, false>, cudaFuncAttributeMaxDynamicSharedMemorySize, GSMEM);

    const int GY = N / TBM;   // 256
    cudaStream_t sM = 0, sP = g_s2, sC = g_s3, sD = g_s4;

    // ---- fork: bring side streams into the capture graph ----
    cudaEventRecord(g_evF, sM);
    cudaStreamWaitEvent(sP, g_evF, 0);
    cudaStreamWaitEvent(sC, g_evF, 0);
    cudaStreamWaitEvent(sD, g_evF, 0);

    auto prt = [&](const float* in, float* o, int Kin, int Nn, int Kpad, int addI,
                   cudaStream_t st) {
        int tot = Nn * Kpad;
        padround_t_k<<<(tot + 255) / 256, 256, 0, st>>>(in, o, Kin, Nn, Kpad, addI);
    };

    // ============ MOL prep on sC: CSC + layer/out/head weight transposes ======
    zero_i_k<<<(N + 255) / 256, 256, 0, sC>>>(cnt, N);
    count_k<<<(E_MOL + 255) / 256, 256, 0, sC>>>(mol_ei + E_MOL, E_MOL, cnt);
    scan_k<<<1, 1024, 0, sC>>>(cnt, offm, cur, dism, N);
    scatter_k<<<(E_MOL + 255) / 256, 256, 0, sC>>>(mol_ei, mol_ei + E_MOL, E_MOL, cur, cscm);
    for (int l = 0; l < LAYERS; l++)
        prt(mol_ws + (size_t)l * HID * HID, wts + WS_M + (size_t)l * HID * HID, HID, HID, HID, 1, sC);
    prt(mol_w_out, wts + WOUT_M, HID, OUT_D, HID, 0, sC);
    prt(w_fc1, wts + WFC1, 256, 1024, 256, 0, sC);
    prt(w_fc2, wts + WFC2, 1024, 512, 1024, 0, sC);
    cudaEventRecord(g_evPM, sC);

    // ============ PRO prep on sD ============
    zero_i_k<<<(N + 255) / 256, 256, 0, sD>>>(cnt2, N);
    count_k<<<(E_PRO + 255) / 256, 256, 0, sD>>>(pro_ei + E_PRO, E_PRO, cnt2);
    scan_k<<<1, 1024, 0, sD>>>(cnt2, offp, cur2, disp, N);
    scatter_k<<<(E_PRO + 255) / 256, 256, 0, sD>>>(pro_ei, pro_ei + E_PRO, E_PRO, cur2, cscp);
    for (int l = 0; l < LAYERS; l++)
        prt(pro_ws + (size_t)l * HID * HID, wts + WS_P + (size_t)l * HID * HID, HID, HID, HID, 1, sD);
    prt(pro_w_out, wts + WOUT_P, HID, OUT_D, HID, 0, sD);
    cudaEventRecord(g_evPP, sD);

    // =================== MOL chain on sM ===================
    padround_k<<<(N * K_IN + 255) / 256, 256, 0, sM>>>(mol_x, xm, 78, N, K_IN);
    prt(mol_w_in, wts + WIN_M, 78, HID, K_IN, 0, sM);
    gemm2_k<0, true><<<dim3(HID / TBN, GY, 1), 128, GSMEM, sM>>>(
        xm, xm, K_IN, wts + WIN_M, wts + WIN_M, K_IN,
        mol_b_in, mol_b_in, nullptr, nullptr, h0m, h0m, K_IN, HID, 0, 0);

    cudaStreamWaitEvent(sM, g_evPM, 0);   // CSC_m + ws_m ready
    for (int l = 0; l < LAYERS; l++) {
        const float* pin = (l == 0) ? h0m : prvm;
        spmm_k<<<N, 128, 0, sM>>>(pin, h0m, supp, offm, cscm, dism);
        gemm2_k<1, true><<<dim3(HID / TBN, GY, 1), 128, GSMEM, sM>>>(
            supp, supp, HID, wts + WS_M + (size_t)l * HID * HID, wts + WS_M, HID,
            nullptr, nullptr, pin, pin, prvm, prvm, HID, HID, 0, 0);
    }

    // =================== PRO chain on sP ===================
    padround_k<<<(N * K_IN + 255) / 256, 256, 0, sP>>>(pro_x, xp, 54, N, K_IN);
    prt(pro_w_in, wts + WIN_P, 54, HID, K_IN, 0, sP);
    gemm2_k<0, true><<<dim3(HID / TBN, GY, 1), 128, GSMEM, sP>>>(
        xp, xp, K_IN, wts + WIN_P, wts + WIN_P, K_IN,
        pro_b_in, pro_b_in, nullptr, nullptr, h0p, h0p, K_IN, HID, 0, 0);

    cudaStreamWaitEvent(sP, g_evPP, 0);   // CSC_p + ws_p ready
    for (int l = 0; l < LAYERS; l++) {
        const float* pin = (l == 0) ? h0p : prvp;
        spmm_k<<<N, 128, 0, sP>>>(pin, h0p, supp + NH, offp, cscp, disp);
        gemm2_k<1, true><<<dim3(HID / TBN, GY, 1), 128, GSMEM, sP>>>(
            supp + NH, supp + NH, HID, wts + WS_P + (size_t)l * HID * HID, wts + WS_P, HID,
            nullptr, nullptr, pin, pin, prvp, prvp, HID, HID, 0, 0);
    }

    // ---- join ----
    cudaEventRecord(g_evJ, sP);
    cudaStreamWaitEvent(sM, g_evJ, 0);

    // ---- batched output projections into concat buffer [N, 256] ----
    gemm2_k<2, true><<<dim3(OUT_D / TBN, GY, 2), 128, GSMEM, sM>>>(
        prvm, prvp, HID, wts + WOUT_M, wts + WOUT_P, HID,
        mol_b_out, pro_b_out, nullptr, nullptr, cat, cat, HID, 256, 0, OUT_D);

    // ---- MLP head: fc1, then fused fc2+gemv ----
    gemm2_k<0, true><<<dim3(1024 / TBN, GY, 1), 128, GSMEM, sM>>>(
        cat, cat, 256, wts + WFC1, wts + WFC1, 256,
        b_fc1, b_fc1, nullptr, nullptr, fc1, fc1, 256, 1024, 0, 0);
    out_init_k<<<(N + 255) / 256, 256, 0, sM>>>(out, b_o, N);
    gemm2_k<5, false><<<dim3(512 / TBN, GY, 1), 128, GSMEM, sM>>>(
        fc1, fc1, 1024, wts + WFC2, wts + WFC2, 1024,
        b_fc2, b_fc2, w_o, w_o, out, out, 1024, 0, 0, 0);
}